// round 5
// baseline (speedup 1.0000x reference)
#include <cuda_runtime.h>

// CplxGaussianRBF: out[b,c,p,{re,im}] = sum_w exp(-|x[b,c,p]-mu[w]|^2/(2*sd[w])) * w_{re,im}[c,w] + bias
// B=4, C=32, H=W=64 (HW=4096), NW=64.
//
// Layout: 1024 blocks x 256 threads; each block owns 512 contiguous pixels of one
// (b,c) slice (8 blocks per slice). Each thread computes 2 adjacent pixels
// (float2 loads, float4 interleaved store). Per-slice constants (mu_r, mu_i,
// coef = -log2e/(2*sd), w_r[c], w_i[c]) staged in shared memory, read back as
// float4 to keep LDS off the critical path. exp(-d/(2s)) computed as a single
// FMUL + ex2.approx (scale folded into coef).

#define CN   32
#define HWN  4096
#define NWN  64

__global__ __launch_bounds__(256, 4)
void cplx_rbf_kernel(
    const float* __restrict__ xr, const float* __restrict__ xi,
    const float* __restrict__ wr, const float* __restrict__ wi,
    const float* __restrict__ br, const float* __restrict__ bi,
    const float* __restrict__ mur, const float* __restrict__ mui,
    const float* __restrict__ sd,
    float* __restrict__ out)
{
    __shared__ __align__(16) float s_mur[NWN];
    __shared__ __align__(16) float s_mui[NWN];
    __shared__ __align__(16) float s_cf [NWN];
    __shared__ __align__(16) float s_wr [NWN];
    __shared__ __align__(16) float s_wi [NWN];

    const int t  = threadIdx.x;
    const int bc = blockIdx.x >> 3;           // (b*C + c) slice index
    const int c  = bc & (CN - 1);

    if (t < NWN) {
        s_mur[t] = mur[t];
        s_mui[t] = mui[t];
        // exp(-d/(2*sd)) = 2^(d * (-log2(e)/(2*sd)))
        s_cf[t]  = -0.7213475204444817f / sd[t];
        s_wr[t]  = wr[c * NWN + t];
        s_wi[t]  = wi[c * NWN + t];
    }
    __syncthreads();

    const int p0   = ((blockIdx.x & 7) << 9) + (t << 1);   // pixel pair within slice
    const int base = bc * HWN;

    const float2 x_r = *reinterpret_cast<const float2*>(xr + base + p0);
    const float2 x_i = *reinterpret_cast<const float2*>(xi + base + p0);

    float ar0 = 0.f, ai0 = 0.f, ar1 = 0.f, ai1 = 0.f;

#define RBF_STEP(MR, MI, CF, WR, WI)                                   \
    {                                                                  \
        float dr0 = x_r.x - (MR), di0 = x_i.x - (MI);                  \
        float dr1 = x_r.y - (MR), di1 = x_i.y - (MI);                  \
        float d0  = fmaf(di0, di0, dr0 * dr0) * (CF);                  \
        float d1  = fmaf(di1, di1, dr1 * dr1) * (CF);                  \
        float e0, e1;                                                  \
        asm("ex2.approx.f32 %0, %1;" : "=f"(e0) : "f"(d0));            \
        asm("ex2.approx.f32 %0, %1;" : "=f"(e1) : "f"(d1));            \
        ar0 = fmaf(e0, (WR), ar0);  ai0 = fmaf(e0, (WI), ai0);         \
        ar1 = fmaf(e1, (WR), ar1);  ai1 = fmaf(e1, (WI), ai1);         \
    }

#pragma unroll
    for (int w = 0; w < NWN; w += 4) {
        const float4 m_r = *reinterpret_cast<const float4*>(s_mur + w);
        const float4 m_i = *reinterpret_cast<const float4*>(s_mui + w);
        const float4 cf  = *reinterpret_cast<const float4*>(s_cf  + w);
        const float4 w_r = *reinterpret_cast<const float4*>(s_wr  + w);
        const float4 w_i = *reinterpret_cast<const float4*>(s_wi  + w);
        RBF_STEP(m_r.x, m_i.x, cf.x, w_r.x, w_i.x);
        RBF_STEP(m_r.y, m_i.y, cf.y, w_r.y, w_i.y);
        RBF_STEP(m_r.z, m_i.z, cf.z, w_r.z, w_i.z);
        RBF_STEP(m_r.w, m_i.w, cf.w, w_r.w, w_i.w);
    }
#undef RBF_STEP

    const float brc = br[c];
    const float bic = bi[c];

    float4 o;
    o.x = ar0 + brc;  // pixel p0   real
    o.y = ai0 + bic;  // pixel p0   imag
    o.z = ar1 + brc;  // pixel p0+1 real
    o.w = ai1 + bic;  // pixel p0+1 imag
    *reinterpret_cast<float4*>(out + (size_t)(base + p0) * 2) = o;
}

extern "C" void kernel_launch(void* const* d_in, const int* in_sizes, int n_in,
                              void* d_out, int out_size)
{
    const float* xr  = (const float*)d_in[0];  // x_real  (4,32,64,64)
    const float* xi  = (const float*)d_in[1];  // x_imag
    const float* wr  = (const float*)d_in[2];  // w_real  (32,64)
    const float* wi  = (const float*)d_in[3];  // w_imag
    const float* br  = (const float*)d_in[4];  // b_real  (1,32,1)
    const float* bi  = (const float*)d_in[5];  // b_imag
    const float* mur = (const float*)d_in[6];  // mu_real (64)
    const float* mui = (const float*)d_in[7];  // mu_imag (64)
    const float* sd  = (const float*)d_in[8];  // stddev  (64)
    float* out = (float*)d_out;                // (4,32,64,64,2)

    // 4*32*4096 pixels / (256 threads * 2 pixels) = 1024 blocks
    cplx_rbf_kernel<<<1024, 256>>>(xr, xi, wr, wi, br, bi, mur, mui, sd, out);
}

// round 6
// speedup vs baseline: 1.6280x; 1.6280x over previous
#include <cuda_runtime.h>

// CplxGaussianRBF: out[b,c,p,{re,im}] = sum_w exp(-|x[b,c,p]-mu[w]|^2/(2*sd[w])) * w_{re,im}[c,w] + bias
// B=4, C=32, H=W=64 (HW=4096), NW=64.
//
// R5: exponent re-expressed as A*n + B*xr + C*xi + D (A=cf, B=-2cf*mur, C=-2cf*mui,
// D=cf*|mu|^2, n=|x|^2 per pixel) -> 3 FFMA per pixel-weight instead of 7 ops.
// Both pixels of a thread packed into Blackwell f32x2 lanes (fma.rn.f32x2 / FFMA2),
// halving fma-pipe issue again. Coefficients stored in smem pre-duplicated
// ({A,A,B,B} etc.) so LDS.128 yields packed 64-bit operands directly — no mov packs.
// MUFU (ex2.approx, 2 per weight) becomes the limiting pipe.

#define CN   32
#define HWN  4096
#define NWN  64

__device__ __forceinline__ unsigned long long fma2(unsigned long long a,
                                                   unsigned long long b,
                                                   unsigned long long c) {
    unsigned long long d;
    asm("fma.rn.f32x2 %0, %1, %2, %3;" : "=l"(d) : "l"(a), "l"(b), "l"(c));
    return d;
}
__device__ __forceinline__ unsigned long long pack2(float lo, float hi) {
    unsigned long long d;
    asm("mov.b64 %0, {%1, %2};" : "=l"(d) : "f"(lo), "f"(hi));
    return d;
}
__device__ __forceinline__ void unpack2(unsigned long long v, float& lo, float& hi) {
    asm("mov.b64 {%0, %1}, %2;" : "=f"(lo), "=f"(hi) : "l"(v));
}

__global__ __launch_bounds__(256)
void cplx_rbf_kernel(
    const float* __restrict__ xr, const float* __restrict__ xi,
    const float* __restrict__ wr, const float* __restrict__ wi,
    const float* __restrict__ br, const float* __restrict__ bi,
    const float* __restrict__ mur, const float* __restrict__ mui,
    const float* __restrict__ sd,
    float* __restrict__ out)
{
    // per weight w: s_ab = {A,A,B,B}, s_cd = {C,C,D,D}, s_wp = {wr,wr,wi,wi}
    __shared__ __align__(16) float s_ab[NWN * 4];
    __shared__ __align__(16) float s_cd[NWN * 4];
    __shared__ __align__(16) float s_wp[NWN * 4];

    const int t  = threadIdx.x;
    const int bc = blockIdx.x >> 3;           // (b*C + c) slice index
    const int c  = bc & (CN - 1);

    if (t < NWN) {
        const float cf = -0.7213475204444817f / sd[t];   // -log2(e)/(2*sd)
        const float mr = mur[t];
        const float mi = mui[t];
        const float A  = cf;
        const float Bq = -2.0f * cf * mr;
        const float Cq = -2.0f * cf * mi;
        const float D  = cf * fmaf(mr, mr, mi * mi);
        const float wrv = wr[c * NWN + t];
        const float wiv = wi[c * NWN + t];
        float4* ab = reinterpret_cast<float4*>(s_ab);
        float4* cd = reinterpret_cast<float4*>(s_cd);
        float4* wp = reinterpret_cast<float4*>(s_wp);
        ab[t] = make_float4(A,  A,  Bq, Bq);
        cd[t] = make_float4(Cq, Cq, D,  D);
        wp[t] = make_float4(wrv, wrv, wiv, wiv);
    }
    __syncthreads();

    const int p0   = ((blockIdx.x & 7) << 9) + (t << 1);   // pixel pair within slice
    const int base = bc * HWN;

    const float2 x_r = *reinterpret_cast<const float2*>(xr + base + p0);
    const float2 x_i = *reinterpret_cast<const float2*>(xi + base + p0);

    const float n0 = fmaf(x_r.x, x_r.x, x_i.x * x_i.x);
    const float n1 = fmaf(x_r.y, x_r.y, x_i.y * x_i.y);

    const unsigned long long xr01 = pack2(x_r.x, x_r.y);
    const unsigned long long xi01 = pack2(x_i.x, x_i.y);
    const unsigned long long n01  = pack2(n0, n1);

    unsigned long long accr = 0ULL;   // {0.0f, 0.0f}
    unsigned long long acci = 0ULL;

    const ulonglong2* ab2 = reinterpret_cast<const ulonglong2*>(s_ab);
    const ulonglong2* cd2 = reinterpret_cast<const ulonglong2*>(s_cd);
    const ulonglong2* wp2 = reinterpret_cast<const ulonglong2*>(s_wp);

#pragma unroll
    for (int w = 0; w < NWN; w++) {
        const ulonglong2 ab = ab2[w];   // .x = {A,A},  .y = {B,B}
        const ulonglong2 cd = cd2[w];   // .x = {C,C},  .y = {D,D}
        const ulonglong2 wp = wp2[w];   // .x = {wr,wr}, .y = {wi,wi}

        unsigned long long e = fma2(ab.x, n01,  cd.y);   // A*n + D
        e = fma2(ab.y, xr01, e);                         // + B*xr
        e = fma2(cd.x, xi01, e);                         // + C*xi

        float t0, t1;
        unpack2(e, t0, t1);
        float e0, e1;
        asm("ex2.approx.f32 %0, %1;" : "=f"(e0) : "f"(t0));
        asm("ex2.approx.f32 %0, %1;" : "=f"(e1) : "f"(t1));
        const unsigned long long e01 = pack2(e0, e1);

        accr = fma2(e01, wp.x, accr);
        acci = fma2(e01, wp.y, acci);
    }

    float ar0, ar1, ai0, ai1;
    unpack2(accr, ar0, ar1);
    unpack2(acci, ai0, ai1);

    const float brc = br[c];
    const float bic = bi[c];

    float4 o;
    o.x = ar0 + brc;  // pixel p0   real
    o.y = ai0 + bic;  // pixel p0   imag
    o.z = ar1 + brc;  // pixel p0+1 real
    o.w = ai1 + bic;  // pixel p0+1 imag
    *reinterpret_cast<float4*>(out + (size_t)(base + p0) * 2) = o;
}

extern "C" void kernel_launch(void* const* d_in, const int* in_sizes, int n_in,
                              void* d_out, int out_size)
{
    const float* xr  = (const float*)d_in[0];  // x_real  (4,32,64,64)
    const float* xi  = (const float*)d_in[1];  // x_imag
    const float* wr  = (const float*)d_in[2];  // w_real  (32,64)
    const float* wi  = (const float*)d_in[3];  // w_imag
    const float* br  = (const float*)d_in[4];  // b_real  (1,32,1)
    const float* bi  = (const float*)d_in[5];  // b_imag
    const float* mur = (const float*)d_in[6];  // mu_real (64)
    const float* mui = (const float*)d_in[7];  // mu_imag (64)
    const float* sd  = (const float*)d_in[8];  // stddev  (64)
    float* out = (float*)d_out;                // (4,32,64,64,2)

    cplx_rbf_kernel<<<1024, 256>>>(xr, xi, wr, wi, br, bi, mur, mui, sd, out);
}